// round 17
// baseline (speedup 1.0000x reference)
#include <cuda_runtime.h>
#include <cuda_bf16.h>

#define N_IN    11008
#define N_OUT   4096
#define TOPK_K  5504
#define N_CACHE 64
#define NBW     344            // ceil(11008/32)
#define TPB     1024
#define GRID    128            // 128 blocks x 32 warps = 4096 warps = 1 row/warp
#define CAP     2048           // candidate list capacity (fast path)
#define TCAP    512            // tie list capacity (fast path)

// ---- device-global scratch (allocation-free; fully rewritten each call) ----
__device__ __align__(16) float g_xm2[N_IN];   // cold-path xm (multiplicities)
__device__ unsigned g_maskbits[NBW];
__device__ int g_tieidx[TOPK_K];   // selected tie indices (usually 1 used)
__device__ int g_inter[N_CACHE];
__device__ unsigned g_Tval;        // threshold bits
__device__ unsigned g_tiecnt;      // number of selected ties (= need)
__device__ unsigned g_decide_val;  // (use<<31)|best
__device__ unsigned g_arrive;      // launch arrival counter (monotonic)
__device__ unsigned g_T_done;      // +1 per launch: T + ties published
__device__ unsigned g_mask_done;   // +1 per launch: maskbits published
__device__ unsigned g_int_done;    // +64 per launch: intersections written
__device__ unsigned g_decide_done; // +1 per launch: decision published
__device__ unsigned g_cold_done;   // +1 per launch IF cold path: xm2 built

__device__ __forceinline__ void poll_ge(const unsigned* addr, unsigned target) {
    unsigned cur;
    for (;;) {
        asm volatile("ld.acquire.gpu.u32 %0, [%1];"
                     : "=r"(cur) : "l"(addr) : "memory");
        if (cur >= target) break;
        __nanosleep(64);
    }
}

// 1024-thread block inclusive scan (one int per thread).
__device__ __forceinline__ int scan1024(int v, int lane, int wid, int* sbuf) {
    __syncthreads();
    #pragma unroll
    for (int o = 1; o < 32; o <<= 1) {
        int t = __shfl_up_sync(0xffffffffu, v, o);
        if (lane >= o) v += t;
    }
    if (lane == 31) sbuf[wid] = v;
    __syncthreads();
    if (wid == 0) {
        int w = sbuf[lane];
        #pragma unroll
        for (int o = 1; o < 32; o <<= 1) {
            int t = __shfl_up_sync(0xffffffffu, w, o);
            if (lane >= o) w += t;
        }
        sbuf[lane] = w;
    }
    __syncthreads();
    if (wid > 0) v += sbuf[wid - 1];
    return v;
}

// ============================================================================
// Mega-kernel, ONE launch, 128 blocks x 1024 threads:
//   block 0:      stage+hist0 -> compact candidates -> tiny levels 1/2 ->
//                 T + tie indices published EARLY -> mask build (for recall)
//   blocks 1..64: cbits -> poll mask -> intersection -> g_int_done++
//   block 65:     poll int==64 -> decision (concurrent with GEMV)
//   ALL blocks:   poll T -> GEMV with inline |x|>T predicate + tie correction
//                 -> read decision -> store (hot) | recompute from xm2 (cold)
// ============================================================================
__global__ void __launch_bounds__(TPB, 1)
mega_kernel(const float* __restrict__ x, const int* __restrict__ cached,
            const float* __restrict__ W, const float* __restrict__ bias,
            float* __restrict__ out) {
    __shared__ unsigned s_mem[N_IN];     // block 0: |x| bits; blocks 1-64: cbits
    __shared__ unsigned hist[2048];
    __shared__ unsigned s_bits[NBW];
    __shared__ unsigned s_cu[CAP];       // candidate |x| bits
    __shared__ int      s_ci[CAP];       // candidate indices
    __shared__ int      s_tie[TCAP];
    __shared__ int scanbuf[32];
    __shared__ int s_b, s_G, s_need, s_ccnt, s_tcnt, s_early;
    __shared__ unsigned s_T, s_gen, s_dec;

    const int b = blockIdx.x, tid = threadIdx.x;
    const int lane = tid & 31, wid = tid >> 5;

    if (tid == 0) s_gen = atomicAdd(&g_arrive, 1u) / GRID;   // launch generation
    __syncthreads();
    const unsigned gen = s_gen;

    if (b == 0) {
        // ---- fused vectorized stage + level-0 histogram (bits [30:21]) ----
        for (int i = tid; i < 2048; i += TPB) hist[i] = 0;
        for (int i = tid; i < NBW; i += TPB) s_bits[i] = 0;
        if (tid == 0) { s_ccnt = 0; s_tcnt = 0; }
        __syncthreads();
        {
            const uint4* x4u = (const uint4*)x;
            uint4* s4 = (uint4*)s_mem;
            for (int i = tid; i < N_IN / 4; i += TPB) {
                uint4 u = x4u[i];
                u.x &= 0x7FFFFFFFu; u.y &= 0x7FFFFFFFu;
                u.z &= 0x7FFFFFFFu; u.w &= 0x7FFFFFFFu;
                s4[i] = u;
                atomicAdd(&hist[u.x >> 21], 1u);
                atomicAdd(&hist[u.y >> 21], 1u);
                atomicAdd(&hist[u.z >> 21], 1u);
                atomicAdd(&hist[u.w >> 21], 1u);
            }
        }
        __syncthreads();
        {
            const int j0 = 2047 - 2 * tid, j1 = j0 - 1;
            const int h0 = hist[j0], h1 = hist[j1];
            int S = scan1024(h0 + h1, lane, wid, scanbuf);
            int excl = S - h0 - h1;
            const int Kr = TOPK_K;
            if (excl + h0 >= Kr && excl < Kr)   { s_b = j0; s_G = excl; }
            else if (S >= Kr && excl + h0 < Kr) { s_b = j1; s_G = excl + h0; }
        }
        __syncthreads();
        const int b0 = s_b, G0 = s_G;

        // ---- compact candidates (digit0 == b0) ----
        const int CH = (N_IN + TPB - 1) / TPB;   // 11
        const int cstart = tid * CH;
        const int cend   = min(cstart + CH, N_IN);
        for (int i = cstart; i < cend; i++) {
            unsigned u = s_mem[i];
            if ((int)(u >> 21) == b0) {
                int p = atomicAdd(&s_ccnt, 1);
                if (p < CAP) { s_cu[p] = u; s_ci[p] = i; }
            }
        }
        __syncthreads();
        const int cnt = s_ccnt;

        if (cnt <= CAP) {
            // ---- FAST level 1 over candidates (bits [20:10]) ----
            for (int i = tid; i < 2048; i += TPB) hist[i] = 0;
            __syncthreads();
            for (int p = tid; p < cnt; p += TPB)
                atomicAdd(&hist[(s_cu[p] >> 10) & 0x7FF], 1u);
            __syncthreads();
            {
                const int j0 = 2047 - 2 * tid, j1 = j0 - 1;
                const int h0 = hist[j0], h1 = hist[j1];
                int S = scan1024(h0 + h1, lane, wid, scanbuf);
                int excl = S - h0 - h1;
                const int Kr = TOPK_K - G0;
                if (excl + h0 >= Kr && excl < Kr)   { s_b = j0; s_G = G0 + excl; }
                else if (S >= Kr && excl + h0 < Kr) { s_b = j1; s_G = G0 + excl + h0; }
            }
            __syncthreads();
            const int b1 = s_b, G1 = s_G;

            // ---- FAST level 2 over candidates (bits [9:0]) ----
            __syncthreads();
            for (int i = tid; i < 2048; i += TPB) hist[i] = 0;
            __syncthreads();
            for (int p = tid; p < cnt; p += TPB) {
                unsigned u = s_cu[p];
                if ((int)((u >> 10) & 0x7FF) == b1) atomicAdd(&hist[u & 0x3FF], 1u);
            }
            __syncthreads();
            {
                const int j = 1023 - tid;
                const int h = (int)hist[j];
                int S = scan1024(h, lane, wid, scanbuf);
                int excl = S - h;
                const int Kr = TOPK_K - G1;
                if (S >= Kr && excl < Kr) {
                    s_T = ((unsigned)b0 << 21) | ((unsigned)b1 << 10) | (unsigned)j;
                    s_need = Kr - excl;
                }
            }
            __syncthreads();

            // ---- FAST ties: collect tie candidates, rank by index ----
            for (int p = tid; p < cnt; p += TPB) {
                if (s_cu[p] == s_T) {
                    int q = atomicAdd(&s_tcnt, 1);
                    if (q < TCAP) s_tie[q] = s_ci[p];
                }
            }
            __syncthreads();
            if (tid == 0) s_early = (s_tcnt <= TCAP) ? 1 : 0;
            __syncthreads();
            if (s_early) {
                const int tc = s_tcnt;
                if (tid < tc) {
                    int my = s_tie[tid];
                    int rank = 0;
                    for (int s = 0; s < tc; s++) rank += (s_tie[s] < my);
                    if (rank < s_need) g_tieidx[rank] = my;
                }
                __syncthreads();
                if (tid == 0) {
                    g_Tval = s_T; g_tiecnt = (unsigned)s_need;
                    __threadfence();
                    atomicAdd(&g_T_done, 1u);        // EARLY release: GEMV may start
                }
            }
        } else {
            // ---- FALLBACK: full-scan levels 1 and 2 (rare/adversarial) ----
            if (tid == 0) s_early = 0;
            __syncthreads();
            for (int i = tid; i < 2048; i += TPB) hist[i] = 0;
            __syncthreads();
            for (int i = tid; i < N_IN; i += TPB) {
                unsigned u = s_mem[i];
                if ((int)(u >> 21) == b0) atomicAdd(&hist[(u >> 10) & 0x7FF], 1u);
            }
            __syncthreads();
            {
                const int j0 = 2047 - 2 * tid, j1 = j0 - 1;
                const int h0 = hist[j0], h1 = hist[j1];
                int S = scan1024(h0 + h1, lane, wid, scanbuf);
                int excl = S - h0 - h1;
                const int Kr = TOPK_K - G0;
                if (excl + h0 >= Kr && excl < Kr)   { s_b = j0; s_G = G0 + excl; }
                else if (S >= Kr && excl + h0 < Kr) { s_b = j1; s_G = G0 + excl + h0; }
            }
            __syncthreads();
            const int b1 = s_b, G1 = s_G;
            __syncthreads();
            for (int i = tid; i < 2048; i += TPB) hist[i] = 0;
            __syncthreads();
            const unsigned top22 = ((unsigned)b0 << 21) | ((unsigned)b1 << 10);
            for (int i = tid; i < N_IN; i += TPB) {
                unsigned u = s_mem[i];
                if ((u & 0xFFFFFC00u) == top22) atomicAdd(&hist[u & 0x3FF], 1u);
            }
            __syncthreads();
            {
                const int j = 1023 - tid;
                const int h = (int)hist[j];
                int S = scan1024(h, lane, wid, scanbuf);
                int excl = S - h;
                const int Kr = TOPK_K - G1;
                if (S >= Kr && excl < Kr) { s_T = top22 | (unsigned)j; s_need = Kr - excl; }
            }
            __syncthreads();
        }

        // ---- mask build (for recall); fallback also writes tie indices ----
        const unsigned T = s_T;
        const int need = s_need;
        const int early = s_early;

        int tieCnt = 0;
        for (int i = cstart; i < cend; i++)
            if (s_mem[i] == T) tieCnt++;
        int incl = scan1024(tieCnt, lane, wid, scanbuf);
        int rank = incl - tieCnt;

        for (int i = cstart; i < cend; i++) {
            unsigned u = s_mem[i];
            bool sel;
            if (u > T)       sel = true;
            else if (u == T) {
                sel = (rank < need);
                if (sel && !early) g_tieidx[rank] = i;
                rank++;
            }
            else             sel = false;
            if (sel) atomicOr(&s_bits[i >> 5], 1u << (i & 31));
        }
        __syncthreads();
        for (int i = tid; i < NBW; i += TPB) g_maskbits[i] = s_bits[i];
        __syncthreads();
        if (tid == 0) {
            if (!early) {
                g_Tval = T; g_tiecnt = (unsigned)need;
                __threadfence();
                atomicAdd(&g_T_done, 1u);            // late release (fallback)
            }
            __threadfence();
            atomicAdd(&g_mask_done, 1u);             // release maskbits
        }
    } else if (b <= 64) {
        // ---- cache bitset for cache (b-1), fully concurrent with select ----
        for (int i = tid; i < NBW; i += TPB) s_mem[i] = 0;
        __syncthreads();
        const int* row = cached + (b - 1) * TOPK_K;
        for (int k = tid; k < TOPK_K; k += TPB) {
            int idx = row[k];
            atomicOr(&s_mem[idx >> 5], 1u << (idx & 31));
        }
        __syncthreads();

        if (tid == 0) poll_ge(&g_mask_done, gen + 1u);
        __syncthreads();

        // ---- deduped intersection ----
        int cnt = 0;
        for (int i = tid; i < NBW; i += TPB)
            cnt += __popc(s_mem[i] & g_maskbits[i]);
        #pragma unroll
        for (int o = 16; o; o >>= 1) cnt += __shfl_down_sync(0xffffffffu, cnt, o);
        __syncthreads();
        if (lane == 0) scanbuf[wid] = cnt;
        __syncthreads();
        if (tid == 0) {
            int s = 0;
            #pragma unroll
            for (int i = 0; i < 32; i++) s += scanbuf[i];
            g_inter[b - 1] = s;
            __threadfence();
            atomicAdd(&g_int_done, 1u);
        }
    } else if (b == 65) {
        // ---- decision block: concurrent with everyone's GEMV ----
        if (tid == 0) {
            poll_ge(&g_int_done, (gen + 1u) * 64u);
            float best = -1.0f; int bi = 0;
            #pragma unroll
            for (int i = 0; i < N_CACHE; i++) {
                float r = (float)g_inter[i] / (float)TOPK_K;
                if (r > best) { best = r; bi = i; }
            }
            unsigned use = (best >= 0.9f) ? 1u : 0u;
            s_dec = (use << 31) | (unsigned)bi;
            asm volatile("st.release.gpu.u32 [%0], %1;"
                         :: "l"(&g_decide_val), "r"(s_dec) : "memory");
            __threadfence();
            atomicAdd(&g_decide_done, 1u);
        }
        __syncthreads();
        if (s_dec >> 31) {                           // cold path: build xm2
            for (int i = tid; i < N_IN; i += TPB) g_xm2[i] = 0.0f;
            __syncthreads();
            const int* brow = cached + (s_dec & 0x7FFFFFFFu) * TOPK_K;
            for (int k = tid; k < TOPK_K; k += TPB) {
                int idx = brow[k];
                atomicAdd(&g_xm2[idx], x[idx]);
            }
            __syncthreads();
            if (tid == 0) { __threadfence(); atomicAdd(&g_cold_done, 1u); }
        }
    }

    // ---- ALL blocks: wait only for T (+ties), then GEMV on raw x ----
    if (tid == 0) poll_ge(&g_T_done, gen + 1u);
    __syncthreads();
    const unsigned T = g_Tval;
    const unsigned tiecnt = g_tiecnt;

    const int row = b * 32 + wid;
    const float4* __restrict__ w4 = (const float4*)(W + (long long)row * N_IN);
    const float4* __restrict__ x4 = (const float4*)x;

    float a0 = 0.0f, a1 = 0.0f;
    #pragma unroll 4
    for (int it = 0; it < 43; it++) {
        const int j = lane + it * 64;
        float4 w  = __ldcs(w4 + j);
        float4 v  = x4[j];
        float4 w2 = __ldcs(w4 + j + 32);
        float4 v2 = x4[j + 32];
        a0 += ((__float_as_uint(v.x) & 0x7FFFFFFFu) > T ? w.x * v.x : 0.0f)
            + ((__float_as_uint(v.y) & 0x7FFFFFFFu) > T ? w.y * v.y : 0.0f);
        a1 += ((__float_as_uint(v.z) & 0x7FFFFFFFu) > T ? w.z * v.z : 0.0f)
            + ((__float_as_uint(v.w) & 0x7FFFFFFFu) > T ? w.w * v.w : 0.0f);
        a0 += ((__float_as_uint(v2.x) & 0x7FFFFFFFu) > T ? w2.x * v2.x : 0.0f)
            + ((__float_as_uint(v2.y) & 0x7FFFFFFFu) > T ? w2.y * v2.y : 0.0f);
        a1 += ((__float_as_uint(v2.z) & 0x7FFFFFFFu) > T ? w2.z * v2.z : 0.0f)
            + ((__float_as_uint(v2.w) & 0x7FFFFFFFu) > T ? w2.w * v2.w : 0.0f);
    }
    float acc = a0 + a1;
    // tie correction: the `need` selected threshold-equal elements
    for (unsigned k = lane; k < tiecnt; k += 32) {
        int idx = g_tieidx[k];
        acc += W[(long long)row * N_IN + idx] * x[idx];
    }
    #pragma unroll
    for (int o = 16; o; o >>= 1) acc += __shfl_down_sync(0xffffffffu, acc, o);

    // ---- decision (ready long before the GEMV finished) ----
    if (tid == 0) {
        poll_ge(&g_decide_done, gen + 1u);
        unsigned d;
        asm volatile("ld.acquire.gpu.u32 %0, [%1];"
                     : "=r"(d) : "l"(&g_decide_val) : "memory");
        s_dec = d;
    }
    __syncthreads();

    if (!(s_dec >> 31)) {
        if (lane == 0) out[row] = acc + bias[row];   // hot path
    } else {
        if (tid == 0) poll_ge(&g_cold_done, gen + 1u);
        __syncthreads();
        const float4* __restrict__ x4b = (const float4*)g_xm2;
        float c0 = 0.0f, c1 = 0.0f;
        #pragma unroll 4
        for (int it = 0; it < 43; it++) {
            const int j = lane + it * 64;
            float4 w  = w4[j];
            float4 v  = x4b[j];
            c0 += w.x * v.x + w.y * v.y;
            c1 += w.z * v.z + w.w * v.w;
            float4 w2 = w4[j + 32];
            float4 v2 = x4b[j + 32];
            c0 += w2.x * v2.x + w2.y * v2.y;
            c1 += w2.z * v2.z + w2.w * v2.w;
        }
        float cacc = c0 + c1;
        #pragma unroll
        for (int o = 16; o; o >>= 1) cacc += __shfl_down_sync(0xffffffffu, cacc, o);
        if (lane == 0) out[row] = cacc + bias[row];
    }
}

// ============================================================================
extern "C" void kernel_launch(void* const* d_in, const int* in_sizes, int n_in,
                              void* d_out, int out_size) {
    const float* x      = (const float*)d_in[0];
    const float* W      = (const float*)d_in[1];
    const float* bias   = (const float*)d_in[2];
    const int*   cached = (const int*)d_in[3];
    float*       out    = (float*)d_out;

    mega_kernel<<<GRID, TPB>>>(x, cached, W, bias, out);
}